// round 7
// baseline (speedup 1.0000x reference)
#include <cuda_runtime.h>
#include <cuda_fp16.h>
#include <cstdint>

#define NPTS 50000
#define CH_IN 512
#define PP 128
#define KNB 27
#define EPSV 1e-5f

typedef __half half_t;

#define NROWT64  ((NPTS + 63) / 64)     // 782
#define NROWT128 ((NPTS + 127) / 128)   // 391

// ---------------- scratch (device globals) ----------------------------------
__device__ float  g_bufA[(size_t)NPTS * PP];
__device__ half_t g_xh[(size_t)NPTS * CH_IN];
__device__ half_t g_hh[(size_t)NPTS * PP];
__device__ half_t g_w1h[PP * CH_IN];        // [128 n][512 k]
__device__ half_t g_w2h[PP * KNB * PP];     // [128 n][3456 k]
__device__ half_t g_w3h[CH_IN * PP];        // [512 n][128 k]
__device__ float  g_valid[NPTS];
__device__ float  g_ratio[NPTS];
__device__ float  g_m2[NPTS];
__device__ float2 g_part2[(size_t)NROWT128 * CH_IN];   // >= NROWT64*PP
__device__ float  g_mu[CH_IN];
__device__ float  g_rs[CH_IN];

// ---------------- PTX helpers ------------------------------------------------
__device__ __forceinline__ uint32_t smem_u32(const void* p) {
    uint32_t a;
    asm("{ .reg .u64 t; cvta.to.shared.u64 t, %1; cvt.u32.u64 %0, t; }" : "=r"(a) : "l"(p));
    return a;
}
#define CP16(dst, src) asm volatile("cp.async.cg.shared.global [%0], [%1], 16;" :: "r"(dst), "l"(src) : "memory")
#define CP_COMMIT()    asm volatile("cp.async.commit_group;" ::: "memory")
template <int N>
__device__ __forceinline__ void cp_wait() {
    asm volatile("cp.async.wait_group %0;" :: "n"(N) : "memory");
}

__device__ __forceinline__ void ldm4(uint32_t* r, uint32_t a) {
    asm volatile("ldmatrix.sync.aligned.m8n8.x4.shared.b16 {%0,%1,%2,%3}, [%4];"
                 : "=r"(r[0]), "=r"(r[1]), "=r"(r[2]), "=r"(r[3]) : "r"(a));
}
__device__ __forceinline__ void mma16816(float* c, const uint32_t* a, const uint32_t* b) {
    asm volatile("mma.sync.aligned.m16n8k16.row.col.f32.f16.f16.f32 "
                 "{%0,%1,%2,%3}, {%4,%5,%6,%7}, {%8,%9}, {%0,%1,%2,%3};"
                 : "+f"(c[0]), "+f"(c[1]), "+f"(c[2]), "+f"(c[3])
                 : "r"(a[0]), "r"(a[1]), "r"(a[2]), "r"(a[3]), "r"(b[0]), "r"(b[1]));
}

// ---------------- small kernels ----------------------------------------------
__global__ void valid_kernel(const float* __restrict__ mask) {
    int n = blockIdx.x * blockDim.x + threadIdx.x;
    if (n < NPTS) g_valid[n] = mask[n] > 0.f ? 1.f : 0.f;
}
__global__ void ratio_kernel(const float* __restrict__ mask, const int* __restrict__ nbr,
                             float* __restrict__ mout) {
    int n = blockIdx.x * blockDim.x + threadIdx.x;
    if (n >= NPTS) return;
    float s = 0.f;
#pragma unroll
    for (int k = 0; k < KNB; k++) s += g_valid[nbr[(size_t)n * KNB + k]];
    float has = s > 0.f ? 1.f : 0.f;
    g_ratio[n] = has * (27.f / fmaxf(s, 1.f));
    g_m2[n] = has;
    mout[n] = fminf(has + mask[n], 1.f);
}
__global__ void convert_x(const float* __restrict__ x) {
    size_t i = (size_t)blockIdx.x * blockDim.x + threadIdx.x;
    if (i < (size_t)NPTS * CH_IN) g_xh[i] = __float2half_rn(x[i]);
}
#define W1E (PP * CH_IN)
#define W2E (PP * KNB * PP)
#define W3E (CH_IN * PP)
__global__ void prep_w(const float* __restrict__ W1, const float* __restrict__ W2,
                       const float* __restrict__ W3) {
    int i = blockIdx.x * blockDim.x + threadIdx.x;
    if (i < W1E) {                    // [512,128] -> [128 n][512 k]
        int n = i / CH_IN, k = i % CH_IN;
        g_w1h[i] = __float2half_rn(W1[(size_t)k * PP + n]);
    } else if (i < W1E + W2E) {       // [27*128,128] -> [128 n][3456 k]
        int j = i - W1E;
        int n = j / (KNB * PP), kk = j % (KNB * PP);
        g_w2h[j] = __float2half_rn(W2[(size_t)kk * PP + n]);
    } else if (i < W1E + W2E + W3E) { // [128,512] -> [512 n][128 k]
        int j = i - W1E - W2E;
        int n = j / PP, k = j % PP;
        g_w3h[j] = __float2half_rn(W3[(size_t)k * CH_IN + n]);
    }
}
__global__ void stats_final(const float2* __restrict__ part, int C, int M, int nslots) {
    int c = threadIdx.x;
    float s = 0.f, q = 0.f;
    for (int r = 0; r < nslots; r++) {
        float2 v = part[(size_t)r * C + c];
        s += v.x; q += v.y;
    }
    float mu = s / (float)M;
    float var = q / (float)M - mu * mu;
    g_mu[c] = mu;
    g_rs[c] = rsqrtf(fmaxf(var, 0.f) + EPSV);
}
__global__ void ew_split(const float* __restrict__ in, int use_mask) {
    int idx = blockIdx.x * blockDim.x + threadIdx.x;
    if (idx >= NPTS * PP) return;
    int c = idx & (PP - 1);
    int n = idx >> 7;
    float v = (in[idx] - g_mu[c]) * g_rs[c];
    v = v >= 0.f ? v : 0.1f * v;
    if (use_mask) v *= g_valid[n];
    g_hh[idx] = __float2half_rn(v);
}
__global__ void ew_final(const float* __restrict__ x, float* __restrict__ outp) {
    size_t idx = (size_t)blockIdx.x * blockDim.x + threadIdx.x;
    if (idx >= (size_t)NPTS * CH_IN) return;
    int c = (int)(idx & (CH_IN - 1));
    float v = (outp[idx] - g_mu[c]) * g_rs[c] + x[idx];
    outp[idx] = v >= 0.f ? v : 0.1f * v;
}

// ---------------- HMMA GEMM (templated on M-tile / stages) -------------------
// C[M,N] = A[M,Kd] @ B[N,Kd]^T, fp16 operands, fp32 acc.
// MT x 128 CTA tile, 8 warps, K-chunk 64, NS-stage cp.async.
// MT=64: warp tile 32x32, 2-stage, 3 CTAs/SM.  MT=128: 64x32, 3-stage, 2/SM.
// Fused epilogue: *rowscale, store, deterministic per-CTA column sum/sumsq.
template <int MT, int NS>
__global__ __launch_bounds__(256, (MT == 64) ? 3 : 2) void mma_gemm(
    const half_t* __restrict__ Ah, int lda,
    const int* __restrict__ nbr,
    const half_t* __restrict__ Bh, int ldb,
    float* __restrict__ C, int ldc, int M, int Kd,
    const float* __restrict__ rowscale,
    float2* __restrict__ part, int partC) {
    constexpr uint32_t STAGE = MT * 128 + 16384;
    constexpr uint32_t OFF_B = MT * 128;
    constexpr uint32_t OFF_SN = NS * STAGE;
    constexpr int MI = MT / 32;

    extern __shared__ char smem[];
    const uint32_t sb = smem_u32(smem);
    const int tid = threadIdx.x;
    const int row0 = blockIdx.y * MT;
    const int col0 = blockIdx.x * 128;
    int* snbr = (int*)(smem + OFF_SN);

    if (nbr) {
        for (int i = tid; i < MT * KNB; i += 256) {
            int r = i / KNB, k = i - r * KNB;
            int gr = row0 + r;
            snbr[i] = (gr < M) ? nbr[(size_t)gr * KNB + k] : 0;
        }
        __syncthreads();
    }

    const int w = tid >> 5, l = tid & 31;
    const int wm = (w & 1) * (MT / 2), wn = (w >> 1) * 32;
    const int a7 = l & 7;
    const int lkA = (l >> 4) & 1, lkB = (l >> 3) & 1;
    uint32_t aRow[MI], bRow[2];
#pragma unroll
    for (int i = 0; i < MI; i++) aRow[i] = (uint32_t)(wm + 16 * i + (l & 15)) << 7;
#pragma unroll
    for (int j = 0; j < 2; j++) bRow[j] = (uint32_t)(wn + 16 * j + (l & 7) + ((l & 16) >> 1)) << 7;

    float acc[MI][4][4];
#pragma unroll
    for (int i = 0; i < MI; i++)
#pragma unroll
        for (int n = 0; n < 4; n++)
#pragma unroll
            for (int q = 0; q < 4; q++) acc[i][n][q] = 0.f;

    const int nch = Kd >> 6;

    auto load_chunk = [&](int ch) {
        const int k0 = ch << 6;
        const int kn = ch >> 1;
        const int c0 = (ch & 1) << 6;
        const uint32_t sbase = sb + (uint32_t)(ch % NS) * STAGE;
        for (int i = tid; i < (MT + 128) * 8; i += 256) {
            if (i < MT * 8) {
                const int r = i >> 3, seg = i & 7;
                const uint32_t sw = ((uint32_t)r << 7) + (uint32_t)((seg ^ (r & 7)) << 4);
                size_t arow, acol;
                if (nbr) { arow = (size_t)snbr[r * KNB + kn]; acol = c0; }
                else     { arow = (size_t)min(row0 + r, M - 1); acol = k0; }
                CP16(sbase + sw, Ah + arow * (size_t)lda + acol + (seg << 3));
            } else {
                const int j = i - MT * 8;
                const int r = j >> 3, seg = j & 7;
                const uint32_t sw = ((uint32_t)r << 7) + (uint32_t)((seg ^ (r & 7)) << 4);
                CP16(sbase + OFF_B + sw, Bh + (size_t)(col0 + r) * (size_t)ldb + k0 + (seg << 3));
            }
        }
    };

#pragma unroll
    for (int p = 0; p < NS - 1; p++) {
        if (p < nch) load_chunk(p);
        CP_COMMIT();
    }

    for (int ch = 0; ch < nch; ch++) {
        if (ch + NS - 1 < nch) load_chunk(ch + NS - 1);
        CP_COMMIT();
        cp_wait<NS - 1>();
        __syncthreads();

        const uint32_t bA = sb + (uint32_t)(ch % NS) * STAGE;
#pragma unroll
        for (int s = 0; s < 4; s++) {
            uint32_t ah[MI][4], bh[2][4];
            const uint32_t kwA = (uint32_t)((s << 1) | lkA);
            const uint32_t kwB = (uint32_t)((s << 1) | lkB);
#pragma unroll
            for (int i = 0; i < MI; i++)
                ldm4(ah[i], bA + aRow[i] + ((kwA ^ (uint32_t)a7) << 4));
#pragma unroll
            for (int j = 0; j < 2; j++)
                ldm4(bh[j], bA + OFF_B + bRow[j] + ((kwB ^ (uint32_t)a7) << 4));
#pragma unroll
            for (int i = 0; i < MI; i++)
#pragma unroll
                for (int n = 0; n < 4; n++)
                    mma16816(acc[i][n], ah[i], &bh[n >> 1][(n & 1) * 2]);
        }
        __syncthreads();
    }

    // ---- fused epilogue: scale, store, per-CTA column partial stats ----
    float csum[8], csq[8];
#pragma unroll
    for (int j = 0; j < 8; j++) { csum[j] = 0.f; csq[j] = 0.f; }
#pragma unroll
    for (int i = 0; i < MI; i++) {
#pragma unroll
        for (int hf = 0; hf < 2; hf++) {
            const int r = row0 + wm + 16 * i + 8 * hf + (l >> 2);
            const float sc = (r < M) ? rowscale[r] : 0.f;
            float* cp = C + (size_t)r * ldc + col0 + wn + 2 * (l & 3);
#pragma unroll
            for (int n = 0; n < 4; n++) {
                float v0 = acc[i][n][2 * hf] * sc;
                float v1 = acc[i][n][2 * hf + 1] * sc;
                csum[2 * n]     += v0; csq[2 * n]     += v0 * v0;
                csum[2 * n + 1] += v1; csq[2 * n + 1] += v1 * v1;
                if (r < M) *(float2*)(cp + 8 * n) = make_float2(v0, v1);
            }
        }
    }
#pragma unroll
    for (int d = 4; d < 32; d <<= 1) {
#pragma unroll
        for (int j = 0; j < 8; j++) {
            csum[j] += __shfl_xor_sync(0xFFFFFFFFu, csum[j], d);
            csq[j]  += __shfl_xor_sync(0xFFFFFFFFu, csq[j], d);
        }
    }
    float2* red = (float2*)(smem + OFF_SN);   // snbr no longer needed
    __syncthreads();
    if (l < 4) {
#pragma unroll
        for (int j = 0; j < 8; j++) {
            int col_local = 8 * (j >> 1) + 2 * l + (j & 1);
            red[w * 32 + col_local] = make_float2(csum[j], csq[j]);
        }
    }
    __syncthreads();
    if (tid < 128) {
        int c = tid, q = c >> 5, lo = c & 31;
        float2 a = red[(2 * q) * 32 + lo];
        float2 b = red[(2 * q + 1) * 32 + lo];
        part[(size_t)blockIdx.y * partC + col0 + c] = make_float2(a.x + b.x, a.y + b.y);
    }
}

#define SMEM64  (2 * (64 * 128 + 16384) + 64 * KNB * 4)     // 56064
#define SMEM128 (3 * (128 * 128 + 16384) + 128 * KNB * 4)   // 112128

// ---------------- launch ------------------------------------------------------
extern "C" void kernel_launch(void* const* d_in, const int* in_sizes, int n_in,
                              void* d_out, int out_size) {
    const float* x    = (const float*)d_in[0];
    const float* mask = (const float*)d_in[1];
    const int*   nbr  = (const int*)d_in[2];
    const float* W1   = (const float*)d_in[3];
    const float* W2   = (const float*)d_in[4];
    const float* W3   = (const float*)d_in[5];
    float* out  = (float*)d_out;
    float* mout = out + (size_t)NPTS * CH_IN;

    cudaFuncSetAttribute(mma_gemm<64, 2>,  cudaFuncAttributeMaxDynamicSharedMemorySize, SMEM64);
    cudaFuncSetAttribute(mma_gemm<128, 3>, cudaFuncAttributeMaxDynamicSharedMemorySize, SMEM128);

    float *pA, *pValid, *pRatio, *pM2;
    float2* pPart;
    half_t *pxh, *phh, *pw1h, *pw2h, *pw3h;
    cudaGetSymbolAddress((void**)&pA, g_bufA);
    cudaGetSymbolAddress((void**)&pValid, g_valid);
    cudaGetSymbolAddress((void**)&pRatio, g_ratio);
    cudaGetSymbolAddress((void**)&pM2, g_m2);
    cudaGetSymbolAddress((void**)&pPart, g_part2);
    cudaGetSymbolAddress((void**)&pxh, g_xh);
    cudaGetSymbolAddress((void**)&phh, g_hh);
    cudaGetSymbolAddress((void**)&pw1h, g_w1h);
    cudaGetSymbolAddress((void**)&pw2h, g_w2h);
    cudaGetSymbolAddress((void**)&pw3h, g_w3h);

    const int nb = (NPTS + 255) / 256;
    valid_kernel<<<nb, 256>>>(mask);
    ratio_kernel<<<nb, 256>>>(mask, nbr, mout);
    convert_x<<<(int)(((size_t)NPTS * CH_IN + 255) / 256), 256>>>(x);
    prep_w<<<(W1E + W2E + W3E + 255) / 256, 256>>>(W1, W2, W3);

    // conv1: t1 = (x @ W1) * valid   [Kd=512, MT=64]
    mma_gemm<64, 2><<<dim3(1, NROWT64), 256, SMEM64>>>(pxh, CH_IN, nullptr,
        pw1h, CH_IN, pA, PP, NPTS, CH_IN, pValid, pPart, PP);
    stats_final<<<1, PP>>>(pPart, PP, NPTS, NROWT64);
    ew_split<<<(NPTS * PP + 255) / 256, 256>>>(pA, 1);

    // conv2 gathered: Kd = 27*128 = 3456, MT=64
    mma_gemm<64, 2><<<dim3(1, NROWT64), 256, SMEM64>>>(phh, PP, nbr,
        pw2h, KNB * PP, pA, PP, NPTS, KNB * PP, pRatio, pPart, PP);
    stats_final<<<1, PP>>>(pPart, PP, NPTS, NROWT64);
    ew_split<<<(NPTS * PP + 255) / 256, 256>>>(pA, 0);

    // conv3: out = (h2 @ W3) * m2   [N=512 via 4 column tiles, Kd=128, MT=128]
    mma_gemm<128, 3><<<dim3(4, NROWT128), 256, SMEM128>>>(phh, PP, nullptr,
        pw3h, PP, out, CH_IN, NPTS, PP, pM2, pPart, CH_IN);
    stats_final<<<1, CH_IN>>>(pPart, CH_IN, NPTS, NROWT128);
    ew_final<<<(int)(((size_t)NPTS * CH_IN + 255) / 256), 256>>>(x, out);
}

// round 8
// speedup vs baseline: 1.1198x; 1.1198x over previous
#include <cuda_runtime.h>
#include <cuda_fp16.h>
#include <cstdint>

#define NPTS 50000
#define CH_IN 512
#define PP 128
#define KNB 27
#define EPSV 1e-5f

typedef __half half_t;

#define NROWT ((NPTS + 127) / 128)   // 391 row tiles

// ---------------- scratch (device globals) ----------------------------------
__device__ float  g_bufA[(size_t)NPTS * PP];
__device__ float  g_split[2][(size_t)NROWT * 128 * PP];   // split-K partials
__device__ half_t g_xh[(size_t)NPTS * CH_IN];
__device__ half_t g_hh[(size_t)NPTS * PP];
__device__ half_t g_w1h[PP * CH_IN];        // [128 n][512 k]
__device__ half_t g_w2h[PP * KNB * PP];     // [128 n][3456 k]
__device__ half_t g_w3h[CH_IN * PP];        // [512 n][128 k]
__device__ float  g_valid[NPTS];
__device__ float  g_ratio[NPTS];
__device__ float  g_m2[NPTS];
__device__ float2 g_part2[(size_t)NROWT * CH_IN];
__device__ float  g_mu[CH_IN];
__device__ float  g_rs[CH_IN];

// ---------------- PTX helpers ------------------------------------------------
__device__ __forceinline__ uint32_t smem_u32(const void* p) {
    uint32_t a;
    asm("{ .reg .u64 t; cvta.to.shared.u64 t, %1; cvt.u32.u64 %0, t; }" : "=r"(a) : "l"(p));
    return a;
}
#define CP16(dst, src) asm volatile("cp.async.cg.shared.global [%0], [%1], 16;" :: "r"(dst), "l"(src) : "memory")
#define CP_COMMIT()    asm volatile("cp.async.commit_group;" ::: "memory")
#define CP_WAIT0()     asm volatile("cp.async.wait_group 0;" ::: "memory")
#define CP_WAIT1()     asm volatile("cp.async.wait_group 1;" ::: "memory")
#define CP_WAIT2()     asm volatile("cp.async.wait_group 2;" ::: "memory")

__device__ __forceinline__ void ldm4(uint32_t* r, uint32_t a) {
    asm volatile("ldmatrix.sync.aligned.m8n8.x4.shared.b16 {%0,%1,%2,%3}, [%4];"
                 : "=r"(r[0]), "=r"(r[1]), "=r"(r[2]), "=r"(r[3]) : "r"(a));
}
__device__ __forceinline__ void mma16816(float* c, const uint32_t* a, const uint32_t* b) {
    asm volatile("mma.sync.aligned.m16n8k16.row.col.f32.f16.f16.f32 "
                 "{%0,%1,%2,%3}, {%4,%5,%6,%7}, {%8,%9}, {%0,%1,%2,%3};"
                 : "+f"(c[0]), "+f"(c[1]), "+f"(c[2]), "+f"(c[3])
                 : "r"(a[0]), "r"(a[1]), "r"(a[2]), "r"(a[3]), "r"(b[0]), "r"(b[1]));
}

// ---------------- small kernels ----------------------------------------------
__global__ void valid_kernel(const float* __restrict__ mask) {
    int n = blockIdx.x * blockDim.x + threadIdx.x;
    if (n < NPTS) g_valid[n] = mask[n] > 0.f ? 1.f : 0.f;
}
__global__ void ratio_kernel(const float* __restrict__ mask, const int* __restrict__ nbr,
                             float* __restrict__ mout) {
    int n = blockIdx.x * blockDim.x + threadIdx.x;
    if (n >= NPTS) return;
    float s = 0.f;
#pragma unroll
    for (int k = 0; k < KNB; k++) s += g_valid[nbr[(size_t)n * KNB + k]];
    float has = s > 0.f ? 1.f : 0.f;
    g_ratio[n] = has * (27.f / fmaxf(s, 1.f));
    g_m2[n] = has;
    mout[n] = fminf(has + mask[n], 1.f);
}
__global__ void convert_x(const float* __restrict__ x) {
    size_t i = (size_t)blockIdx.x * blockDim.x + threadIdx.x;
    if (i < (size_t)NPTS * CH_IN) g_xh[i] = __float2half_rn(x[i]);
}
#define W1E (PP * CH_IN)
#define W2E (PP * KNB * PP)
#define W3E (CH_IN * PP)
__global__ void prep_w(const float* __restrict__ W1, const float* __restrict__ W2,
                       const float* __restrict__ W3) {
    int i = blockIdx.x * blockDim.x + threadIdx.x;
    if (i < W1E) {                    // [512,128] -> [128 n][512 k]
        int n = i / CH_IN, k = i % CH_IN;
        g_w1h[i] = __float2half_rn(W1[(size_t)k * PP + n]);
    } else if (i < W1E + W2E) {       // [27*128,128] -> [128 n][3456 k]
        int j = i - W1E;
        int n = j / (KNB * PP), kk = j % (KNB * PP);
        g_w2h[j] = __float2half_rn(W2[(size_t)kk * PP + n]);
    } else if (i < W1E + W2E + W3E) { // [128,512] -> [512 n][128 k]
        int j = i - W1E - W2E;
        int n = j / PP, k = j % PP;
        g_w3h[j] = __float2half_rn(W3[(size_t)k * CH_IN + n]);
    }
}
__global__ void stats_final(const float2* __restrict__ part, int C, int M, int nslots) {
    int c = threadIdx.x;
    float s = 0.f, q = 0.f;
    for (int r = 0; r < nslots; r++) {
        float2 v = part[(size_t)r * C + c];
        s += v.x; q += v.y;
    }
    float mu = s / (float)M;
    float var = q / (float)M - mu * mu;
    g_mu[c] = mu;
    g_rs[c] = rsqrtf(fmaxf(var, 0.f) + EPSV);
}
// combine split-K partials: out = (P0+P1)*ratio, plus per-block column stats
__global__ void combine_stats(const float* __restrict__ P0, const float* __restrict__ P1,
                              const float* __restrict__ ratio, float* __restrict__ outp,
                              float2* __restrict__ part) {
    int c = threadIdx.x;          // 128
    int per = (NPTS + gridDim.x - 1) / gridDim.x;
    int r0 = blockIdx.x * per, r1 = min(r0 + per, NPTS);
    float s = 0.f, q = 0.f;
    for (int r = r0; r < r1; r++) {
        size_t idx = (size_t)r * PP + c;
        float v = (P0[idx] + P1[idx]) * ratio[r];
        outp[idx] = v;
        s += v; q += v * v;
    }
    part[(size_t)blockIdx.x * PP + c] = make_float2(s, q);
}
__global__ void ew_split(const float* __restrict__ in, int use_mask) {
    int idx = blockIdx.x * blockDim.x + threadIdx.x;
    if (idx >= NPTS * PP) return;
    int c = idx & (PP - 1);
    int n = idx >> 7;
    float v = (in[idx] - g_mu[c]) * g_rs[c];
    v = v >= 0.f ? v : 0.1f * v;
    if (use_mask) v *= g_valid[n];
    g_hh[idx] = __float2half_rn(v);
}
__global__ void ew_final(const float* __restrict__ x, float* __restrict__ outp) {
    size_t idx = (size_t)blockIdx.x * blockDim.x + threadIdx.x;
    if (idx >= (size_t)NPTS * CH_IN) return;
    int c = (int)(idx & (CH_IN - 1));
    float v = (outp[idx] - g_mu[c]) * g_rs[c] + x[idx];
    outp[idx] = v >= 0.f ? v : 0.1f * v;
}

// ---------------- HMMA GEMM --------------------------------------------------
// C[M,N] = A[M, kc0*64 .. (kc0+nkc)*64] @ B^T, fp16 operands, fp32 acc.
// 128x128 CTA tile, 8 warps of 64x32, K-chunk 64, 3-stage cp.async, 2 CTAs/SM.
// blockIdx.z selects split-K slice: C += z*czstride, chunks [kc0 = z*nkc, +nkc).
// If part != null: fused epilogue *rowscale + deterministic column stats.
// If part == null: raw store (split partial), no rowscale, no stats.
#define STAGE_BYTES 32768
#define OFF_B  16384u
#define OFF_SN (3u * STAGE_BYTES)
#define SMEM_DYN (3 * STAGE_BYTES + 128 * KNB * 4)

__global__ __launch_bounds__(256, 2) void mma_gemm(
    const half_t* __restrict__ Ah, int lda,
    const int* __restrict__ nbr,
    const half_t* __restrict__ Bh, int ldb,
    float* __restrict__ C, size_t czstride, int ldc, int M, int nkc,
    const float* __restrict__ rowscale,
    float2* __restrict__ part, int partC) {
    extern __shared__ char smem[];
    const uint32_t sb = smem_u32(smem);
    const int tid = threadIdx.x;
    const int row0 = blockIdx.y * 128;
    const int col0 = blockIdx.x * 128;
    const int kc0 = blockIdx.z * nkc;
    C += (size_t)blockIdx.z * czstride;
    int* snbr = (int*)(smem + OFF_SN);

    if (nbr) {
        for (int i = tid; i < 128 * KNB; i += 256) {
            int r = i / KNB, k = i - r * KNB;
            int gr = row0 + r;
            snbr[i] = (gr < M) ? nbr[(size_t)gr * KNB + k] : 0;
        }
        __syncthreads();
    }

    const int w = tid >> 5, l = tid & 31;
    const int wm = (w & 1) * 64, wn = (w >> 1) * 32;
    const int a7 = l & 7;
    const int lkA = (l >> 4) & 1, lkB = (l >> 3) & 1;
    uint32_t aRow[4], bRow[2];
#pragma unroll
    for (int i = 0; i < 4; i++) aRow[i] = (uint32_t)(wm + 16 * i + (l & 15)) << 7;
#pragma unroll
    for (int j = 0; j < 2; j++) bRow[j] = (uint32_t)(wn + 16 * j + (l & 7) + ((l & 16) >> 1)) << 7;

    float acc[4][4][4];
#pragma unroll
    for (int i = 0; i < 4; i++)
#pragma unroll
        for (int n = 0; n < 4; n++)
#pragma unroll
            for (int q = 0; q < 4; q++) acc[i][n][q] = 0.f;

    auto load_chunk = [&](int chl, int stage) {
        const int ch = kc0 + chl;
        const int k0 = ch << 6;
        const int kn = ch >> 1;
        const int c0 = (ch & 1) << 6;
        const uint32_t sbase = sb + (uint32_t)stage * STAGE_BYTES;
        for (int i = tid; i < 1024; i += 256) {
            const int r = i >> 3, seg = i & 7;
            const uint32_t sw = ((uint32_t)r << 7) + (uint32_t)((seg ^ (r & 7)) << 4);
            size_t arow, acol;
            if (nbr) { arow = (size_t)snbr[r * KNB + kn]; acol = c0; }
            else     { arow = (size_t)min(row0 + r, M - 1); acol = k0; }
            CP16(sbase + sw, Ah + arow * (size_t)lda + acol + (seg << 3));
            CP16(sbase + OFF_B + sw, Bh + (size_t)(col0 + r) * (size_t)ldb + k0 + (seg << 3));
        }
    };

    load_chunk(0, 0);
    CP_COMMIT();
    if (nkc > 1) { load_chunk(1, 1); CP_COMMIT(); }

    for (int chl = 0; chl < nkc; chl++) {
        const int st = chl % 3;
        if (chl + 2 < nkc)      { load_chunk(chl + 2, (chl + 2) % 3); CP_COMMIT(); CP_WAIT2(); }
        else if (chl + 1 < nkc) { CP_WAIT1(); }
        else                    { CP_WAIT0(); }
        __syncthreads();

        const uint32_t bA = sb + (uint32_t)st * STAGE_BYTES;
#pragma unroll
        for (int s = 0; s < 4; s++) {
            uint32_t ah[4][4], bh[2][4];
            const uint32_t kwA = (uint32_t)((s << 1) | lkA);
            const uint32_t kwB = (uint32_t)((s << 1) | lkB);
#pragma unroll
            for (int i = 0; i < 4; i++)
                ldm4(ah[i], bA + aRow[i] + ((kwA ^ (uint32_t)a7) << 4));
#pragma unroll
            for (int j = 0; j < 2; j++)
                ldm4(bh[j], bA + OFF_B + bRow[j] + ((kwB ^ (uint32_t)a7) << 4));
#pragma unroll
            for (int i = 0; i < 4; i++)
#pragma unroll
                for (int n = 0; n < 4; n++)
                    mma16816(acc[i][n], ah[i], &bh[n >> 1][(n & 1) * 2]);
        }
        __syncthreads();
    }

    if (part == nullptr) {
        // raw partial store (split-K)
#pragma unroll
        for (int i = 0; i < 4; i++) {
#pragma unroll
            for (int hf = 0; hf < 2; hf++) {
                const int r = row0 + wm + 16 * i + 8 * hf + (l >> 2);
                if (r < M) {
                    float* cp = C + (size_t)r * ldc + col0 + wn + 2 * (l & 3);
#pragma unroll
                    for (int n = 0; n < 4; n++)
                        *(float2*)(cp + 8 * n) = make_float2(acc[i][n][2 * hf], acc[i][n][2 * hf + 1]);
                }
            }
        }
        return;
    }

    // ---- fused epilogue: scale, store, per-CTA column partial stats ----
    float csum[8], csq[8];
#pragma unroll
    for (int j = 0; j < 8; j++) { csum[j] = 0.f; csq[j] = 0.f; }
#pragma unroll
    for (int i = 0; i < 4; i++) {
#pragma unroll
        for (int hf = 0; hf < 2; hf++) {
            const int r = row0 + wm + 16 * i + 8 * hf + (l >> 2);
            const float sc = (r < M) ? rowscale[r] : 0.f;
            float* cp = C + (size_t)r * ldc + col0 + wn + 2 * (l & 3);
#pragma unroll
            for (int n = 0; n < 4; n++) {
                float v0 = acc[i][n][2 * hf] * sc;
                float v1 = acc[i][n][2 * hf + 1] * sc;
                csum[2 * n]     += v0; csq[2 * n]     += v0 * v0;
                csum[2 * n + 1] += v1; csq[2 * n + 1] += v1 * v1;
                if (r < M) *(float2*)(cp + 8 * n) = make_float2(v0, v1);
            }
        }
    }
#pragma unroll
    for (int d = 4; d < 32; d <<= 1) {
#pragma unroll
        for (int j = 0; j < 8; j++) {
            csum[j] += __shfl_xor_sync(0xFFFFFFFFu, csum[j], d);
            csq[j]  += __shfl_xor_sync(0xFFFFFFFFu, csq[j], d);
        }
    }
    float2* red = (float2*)(smem + OFF_SN);
    __syncthreads();
    if (l < 4) {
#pragma unroll
        for (int j = 0; j < 8; j++) {
            int col_local = 8 * (j >> 1) + 2 * l + (j & 1);
            red[w * 32 + col_local] = make_float2(csum[j], csq[j]);
        }
    }
    __syncthreads();
    if (tid < 128) {
        int c = tid, q = c >> 5, lo = c & 31;
        float2 a = red[(2 * q) * 32 + lo];
        float2 b = red[(2 * q + 1) * 32 + lo];
        part[(size_t)blockIdx.y * partC + col0 + c] = make_float2(a.x + b.x, a.y + b.y);
    }
}

// ---------------- launch ------------------------------------------------------
extern "C" void kernel_launch(void* const* d_in, const int* in_sizes, int n_in,
                              void* d_out, int out_size) {
    const float* x    = (const float*)d_in[0];
    const float* mask = (const float*)d_in[1];
    const int*   nbr  = (const int*)d_in[2];
    const float* W1   = (const float*)d_in[3];
    const float* W2   = (const float*)d_in[4];
    const float* W3   = (const float*)d_in[5];
    float* out  = (float*)d_out;
    float* mout = out + (size_t)NPTS * CH_IN;

    cudaFuncSetAttribute(mma_gemm, cudaFuncAttributeMaxDynamicSharedMemorySize, SMEM_DYN);

    float *pA, *pSplit, *pValid, *pRatio, *pM2;
    float2* pPart;
    half_t *pxh, *phh, *pw1h, *pw2h, *pw3h;
    cudaGetSymbolAddress((void**)&pA, g_bufA);
    cudaGetSymbolAddress((void**)&pSplit, g_split);
    cudaGetSymbolAddress((void**)&pValid, g_valid);
    cudaGetSymbolAddress((void**)&pRatio, g_ratio);
    cudaGetSymbolAddress((void**)&pM2, g_m2);
    cudaGetSymbolAddress((void**)&pPart, g_part2);
    cudaGetSymbolAddress((void**)&pxh, g_xh);
    cudaGetSymbolAddress((void**)&phh, g_hh);
    cudaGetSymbolAddress((void**)&pw1h, g_w1h);
    cudaGetSymbolAddress((void**)&pw2h, g_w2h);
    cudaGetSymbolAddress((void**)&pw3h, g_w3h);

    const size_t SPLIT_STRIDE = (size_t)NROWT * 128 * PP;

    const int nb = (NPTS + 255) / 256;
    valid_kernel<<<nb, 256>>>(mask);
    ratio_kernel<<<nb, 256>>>(mask, nbr, mout);
    convert_x<<<(int)(((size_t)NPTS * CH_IN + 255) / 256), 256>>>(x);
    prep_w<<<(W1E + W2E + W3E + 255) / 256, 256>>>(W1, W2, W3);

    // conv1: t1 = (x @ W1) * valid   [Kd=512, 8 chunks]
    mma_gemm<<<dim3(1, NROWT), 256, SMEM_DYN>>>(pxh, CH_IN, nullptr,
        pw1h, CH_IN, pA, 0, PP, NPTS, 8, pValid, pPart, PP);
    stats_final<<<1, PP>>>(pPart, PP, NPTS, NROWT);
    ew_split<<<(NPTS * PP + 255) / 256, 256>>>(pA, 1);

    // conv2 gathered: Kd = 3456, split-K=2 (27 chunks each), raw partials
    mma_gemm<<<dim3(1, NROWT, 2), 256, SMEM_DYN>>>(phh, PP, nbr,
        pw2h, KNB * PP, pSplit, SPLIT_STRIDE, PP, NPTS, 27, nullptr, nullptr, PP);
    combine_stats<<<512, PP>>>(pSplit, pSplit + SPLIT_STRIDE, pRatio, pA, pPart);
    stats_final<<<1, PP>>>(pPart, PP, NPTS, 512);
    ew_split<<<(NPTS * PP + 255) / 256, 256>>>(pA, 0);

    // conv3: out = (h2 @ W3) * m2   [N=512 via 4 column tiles, Kd=128, 2 chunks]
    mma_gemm<<<dim3(4, NROWT), 256, SMEM_DYN>>>(phh, PP, nullptr,
        pw3h, PP, out, 0, CH_IN, NPTS, 2, pM2, pPart, CH_IN);
    stats_final<<<1, CH_IN>>>(pPart, CH_IN, NPTS, NROWT);
    ew_final<<<(int)(((size_t)NPTS * CH_IN + 255) / 256), 256>>>(x, out);
}